// round 17
// baseline (speedup 1.0000x reference)
#include <cuda_runtime.h>
#include <cstdint>

// Fixed problem shape: (N,C,H,W,T) = (8,16,32,32,500)
//
// R15 optimum body (NPER=4, 8 front-batched LDG.128/thread, 32-bit indexing,
// n-half on the high work-unit bit) made PERSISTENT: grid = 148 SMs x 6
// resident blocks = 888 CTAs, each grid-striding over the 16384 work units.
// Eliminates ~15.5k block launches and the partial tail wave.
constexpr int N_ = 8;
constexpr int C_ = 16;
constexpr int H_ = 32;
constexpr int W_ = 32;
constexpr int T_ = 500;
constexpr int CHW = C_ * H_ * W_;     // 16384 (power of two)
constexpr int TV  = T_ / 4;           // 125 float4 per row
constexpr int NPER = 4;               // batch rows per work unit
constexpr int ROWSTRIDE = CHW * TV;   // 2,048,000 float4 stride between n's (32-bit safe)
constexpr int HALF_WORK = CHW / 2;    // 8192 work units per n-half
constexpr int NUM_SMS = 148;
constexpr int BLOCKS_PER_SM = 6;
constexpr int GRID = NUM_SMS * BLOCKS_PER_SM;   // 888 persistent CTAs

__global__ void __launch_bounds__(256, 6) delay_kernel(
    const float* __restrict__ x,
    const float* __restrict__ delay,
    const uint32_t* __restrict__ ts_bits,
    float* __restrict__ out)
{
    int tv   = threadIdx.x & 127;
    int thi  = threadIdx.x >> 7;      // which of the 2 chw lanes in the block
    bool act = tv < TV;

    // Decode Ts robustly (scalar may arrive as int32 or float32 bits).
    uint32_t tb = __ldg(ts_bits);
    float tf = __uint_as_float(tb);
    float Ts = (tf >= 1e-6f && tf <= 1e6f) ? tf : (float)(int)tb;
    float invTs = 1.0f / Ts;

    const float4* __restrict__ x4 = reinterpret_cast<const float4*>(x);
    float4* __restrict__ o4 = reinterpret_cast<float4*>(out);
    float4 z = make_float4(0.f, 0.f, 0.f, 0.f);

    // Grid-stride over work units: low bits = chw pair, high bit = n-half.
    for (int bw = blockIdx.x; bw < CHW; bw += GRID) {
        int bp  = bw & (HALF_WORK - 1);
        int n0  = (bw >= HALF_WORK) ? NPER : 0;
        int chw = (bp << 1) | thi;

        // Per-chw shift parameters — shared by all n.
        float s    = __ldg(delay + chw) * invTs;
        float sif  = floorf(s);
        float frac = s - sif;
        int   si   = (int)sif;

        int start = -1 - si;
        int q0 = start >> 2;
        int r  = start & 3;

        int vi = tv + q0;
        bool va = act && (vi     >= 0) && (vi     < TV);
        bool vb = act && (vi + 1 >= 0) && (vi + 1 < TV);

        int abase = (n0 * CHW + chw) * TV + vi;

        // Front-batched independent loads: 8 x LDG.128 in flight.
        float4 A[NPER], B[NPER];
#pragma unroll
        for (int j = 0; j < NPER; ++j) {
            A[j] = va ? __ldg(x4 + (abase + j * ROWSTRIDE))     : z;
            B[j] = vb ? __ldg(x4 + (abase + j * ROWSTRIDE + 1)) : z;
        }

        float w1 = frac;
        float w0 = 1.0f - frac;
        int obase = (n0 * CHW + chw) * TV + tv;

#pragma unroll
        for (int j = 0; j < NPER; ++j) {
            float l0, l1, l2, l3, l4;
            switch (r) {
                case 0: l0 = A[j].x; l1 = A[j].y; l2 = A[j].z; l3 = A[j].w; l4 = B[j].x; break;
                case 1: l0 = A[j].y; l1 = A[j].z; l2 = A[j].w; l3 = B[j].x; l4 = B[j].y; break;
                case 2: l0 = A[j].z; l1 = A[j].w; l2 = B[j].x; l3 = B[j].y; l4 = B[j].z; break;
                default:l0 = A[j].w; l1 = B[j].x; l2 = B[j].y; l3 = B[j].z; l4 = B[j].w; break;
            }
            float4 o;
            o.x = w0 * l1 + w1 * l0;
            o.y = w0 * l2 + w1 * l1;
            o.z = w0 * l3 + w1 * l2;
            o.w = w0 * l4 + w1 * l3;
            if (act) o4[obase + j * ROWSTRIDE] = o;
        }
    }
}

extern "C" void kernel_launch(void* const* d_in, const int* in_sizes, int n_in,
                              void* d_out, int out_size)
{
    const float*    x     = (const float*)d_in[0];
    const float*    delay = (const float*)d_in[1];
    const uint32_t* ts    = (const uint32_t*)d_in[2];
    float*          out   = (float*)d_out;

    // Persistent launch: 888 CTAs (148 SMs x 6 resident blocks).
    delay_kernel<<<GRID, 256>>>(x, delay, ts, out);
}